// round 6
// baseline (speedup 1.0000x reference)
#include <cuda_runtime.h>
#include <cuda_bf16.h>

// Problem constants (match reference)
#define HH 512
#define WW 512
#define RR 4
#define BB 2
#define PP 65536
#define CC 8
#define NPTS (BB * PP)
#define NPIX (BB * HH * WW)

// Tiling: 8 x 8 pixel tiles, one CTA (64 threads) per tile.
// A 9x9 footprint spans exactly 2x2 tiles -> 4 inserts/point, and the
// per-pixel candidate count shrinks by 33% vs 16x8 tiles.
#define TW 8
#define TH 8
#define TILES_X (WW / TW)              // 64
#define TILES_Y (HH / TH)              // 64
#define TILES_IMG (TILES_X * TILES_Y)  // 4096
#define NTILES (BB * TILES_IMG)        // 8192
#define CAP 192                        // per-tile capacity (mean ~64)

__device__ int g_cnt[NTILES];          // zero at load; gather resets after use
__device__ int g_list[NTILES * CAP];

// ---------------------------------------------------------------------------
// Bin each valid point into every tile its clamped 9x9 pixel box overlaps.
// The exact d2 cull in gather subsumes the box test (min off-box pixel
// distance 4.5 px > max radius 4.09 px), so tile membership is exact.
__global__ void __launch_bounds__(256) k_bin(const float* __restrict__ pts) {
    int i = blockIdx.x * blockDim.x + threadIdx.x;   // NPTS divisible by 256
    float x = pts[3 * i + 0];
    float y = pts[3 * i + 1];
    float z = pts[3 * i + 2];
    if (!(z > 0.1f && z < 10.0f)) return;

    int cx = (int)rintf((x + 1.0f) * 0.5f * 511.0f);
    int cy = (int)rintf((y + 1.0f) * 0.5f * 511.0f);
    int px0 = max(cx - RR, 0), px1 = min(cx + RR, WW - 1);
    int py0 = max(cy - RR, 0), py1 = min(cy + RR, HH - 1);
    if (px0 > px1 || py0 > py1) return;

    int tx0 = px0 >> 3, tx1 = px1 >> 3;              // TW = 8
    int ty0 = py0 >> 3, ty1 = py1 >> 3;              // TH = 8
    int tb = (i >= PP) ? TILES_IMG : 0;

    for (int ty = ty0; ty <= ty1; ++ty)
        for (int tx = tx0; tx <= tx1; ++tx) {
            int t = tb + ty * TILES_X + tx;
            int slot = atomicAdd(&g_cnt[t], 1);
            if (slot < CAP) g_list[t * CAP + slot] = i;
        }
}

// ---------------------------------------------------------------------------
// Gather: one thread per pixel, register accumulators, candidates staged once
// in shared memory. Stabilizer-free weights w' = ws*exp(-2z) (exact
// cancellation in color/depth; EPS influence ~3e-5 rel — verified R2-R5).
// Per-fragment math bit-identical to the passing R1-R5 kernels.
__global__ void __launch_bounds__(64) k_gather(
        const float* __restrict__ pts,
        const float* __restrict__ feat,
        const float* __restrict__ sig,
        const float* __restrict__ mr_ptr,
        float* __restrict__ out) {
    __shared__ float2 sxy[CAP];
    __shared__ float  sz [CAP];
    __shared__ float  sinv[CAP];
    __shared__ float  sez[CAP];
    __shared__ float4 sfa[CAP];
    __shared__ float4 sfb[CAP];

    int t = blockIdx.x;
    int b = t >> 12;                                 // / TILES_IMG (4096)
    int r = t & (TILES_IMG - 1);
    int ty = r >> 6;                                 // / TILES_X (64)
    int tx = r & (TILES_X - 1);

    int tid = threadIdx.x;
    int px = tx * TW + (tid & (TW - 1));
    int py = ty * TH + (tid >> 3);

    // Pixel NDC coords — bit-identical formula to the validated cull math.
    float qxn = __fadd_rn(__fmul_rn(2.0f, (float)px) / 511.0f, -1.0f);
    float qyn = __fadd_rn(__fmul_rn(2.0f, (float)py) / 511.0f, -1.0f);

    float mr = __ldg(mr_ptr);
    float r2 = mr * mr;

    int cnt = g_cnt[t];
    if (cnt > CAP) cnt = CAP;

    const float4* ff = (const float4*)feat;

    // Stage all candidates (strided; single sync pair).
    for (int k = tid; k < cnt; k += 64) {
        int j = g_list[t * CAP + k];
        float x = pts[3 * j + 0];
        float y = pts[3 * j + 1];
        float z = pts[3 * j + 2];
        float s = sig[j];
        sxy[k] = make_float2(x, y);
        sz [k] = z;
        sinv[k] = 1.0f / (2.0f * s * s);
        sez[k] = __expf(-2.0f * z);                  // GAMMA = 0.5
        sfa[k] = ff[2 * j + 0];
        sfb[k] = ff[2 * j + 1];
    }
    __syncthreads();

    float accW = 0.f, accWZ = 0.f, accWS = 0.f;
    float f0 = 0.f, f1 = 0.f, f2 = 0.f, f3 = 0.f;
    float f4v = 0.f, f5 = 0.f, f6 = 0.f, f7 = 0.f;

    for (int k = 0; k < cnt; ++k) {
        float2 pxy = sxy[k];
        float dx = __fadd_rn(qxn, -pxy.x);
        float dy = __fadd_rn(qyn, -pxy.y);
        float d2 = __fadd_rn(__fmul_rn(dx, dx), __fmul_rn(dy, dy));
        if (d2 <= r2) {
            float ws = __expf(-d2 * sinv[k]);
            float w  = ws * sez[k];
            float z  = sz[k];
            accWS += ws;
            accW  += w;
            accWZ += w * z;
            float4 fa = sfa[k];
            float4 fb = sfb[k];
            f0  += w * fa.x;  f1 += w * fa.y;
            f2  += w * fa.z;  f3 += w * fa.w;
            f4v += w * fb.x;  f5 += w * fb.y;
            f6  += w * fb.z;  f7 += w * fb.w;
        }
    }

    // Fused finalize.
    int pix = b * (HH * WW) + py * WW + px;
    float inv = (accW > 0.0f) ? (1.0f / accW) : 0.0f;

    float4* col = (float4*)out;
    col[2 * pix + 0] = make_float4(f0 * inv, f1 * inv, f2 * inv, f3 * inv);
    col[2 * pix + 1] = make_float4(f4v * inv, f5 * inv, f6 * inv, f7 * inv);
    out[NPIX * CC + pix]        = accWZ * inv;           // depth
    out[NPIX * CC + NPIX + pix] = 1.0f - expf(-accWS);   // mask

    // Reset counter for next graph replay. Safe: when cnt>0 every thread's
    // read of g_cnt[t] happened before the __syncthreads above; when cnt==0
    // the store writes the value already present.
    if (tid == 0) g_cnt[t] = 0;
}

// ---------------------------------------------------------------------------
extern "C" void kernel_launch(void* const* d_in, const int* in_sizes, int n_in,
                              void* d_out, int out_size) {
    const float* pts  = (const float*)d_in[0];  // [B,P,3]
    const float* feat = (const float*)d_in[1];  // [B,P,8]
    const float* sig  = (const float*)d_in[2];  // [B,P]
    const float* mr   = (const float*)d_in[3];  // scalar
    float* out = (float*)d_out;

    k_bin   <<<NPTS / 256, 256>>>(pts);
    k_gather<<<NTILES, 64>>>(pts, feat, sig, mr, out);
}

// round 7
// speedup vs baseline: 1.2329x; 1.2329x over previous
#include <cuda_runtime.h>
#include <cuda_bf16.h>

// Problem constants (match reference)
#define HH 512
#define WW 512
#define RR 4
#define BB 2
#define PP 65536
#define CC 8
#define NPTS (BB * PP)
#define NPIX (BB * HH * WW)

// Tiling: 8 x 4 pixel tiles, ONE 32-thread warp-CTA per tile.
// tests/pixel = (8+2R)(4+2R)*density = 192*0.25 = 48.
#define TW 8
#define TH 4
#define TILES_X (WW / TW)              // 64
#define TILES_Y (HH / TH)              // 128
#define TILES_IMG (TILES_X * TILES_Y)  // 8192
#define NTILES (BB * TILES_IMG)        // 16384
#define CAP 128                        // per-tile capacity (mean ~48, sd ~7)
#define CHUNK 32                       // candidates staged per warp round

__device__ int g_cnt[NTILES];          // zero at load; gather resets after use
__device__ int g_list[NTILES * CAP];

// ---------------------------------------------------------------------------
__device__ __forceinline__ unsigned long long pack2(float a, float b) {
    unsigned long long r;
    asm("mov.b64 %0, {%1, %2};" : "=l"(r) : "r"(__float_as_uint(a)), "r"(__float_as_uint(b)));
    return r;
}
__device__ __forceinline__ void unpack2(unsigned long long v, float& a, float& b) {
    unsigned int lo, hi;
    asm("mov.b64 {%0, %1}, %2;" : "=r"(lo), "=r"(hi) : "l"(v));
    a = __uint_as_float(lo);
    b = __uint_as_float(hi);
}
__device__ __forceinline__ void ffma2(unsigned long long& acc,
                                      unsigned long long a,
                                      unsigned long long b) {
    asm("fma.rn.f32x2 %0, %1, %2, %0;" : "+l"(acc) : "l"(a), "l"(b));
}

// ---------------------------------------------------------------------------
// Bin each valid point into every 8x4 tile its clamped 9x9 pixel box overlaps
// (<= 2x3 tiles). The exact d2 cull in gather subsumes the box test.
__global__ void __launch_bounds__(256) k_bin(const float* __restrict__ pts) {
    int i = blockIdx.x * blockDim.x + threadIdx.x;   // NPTS divisible by 256
    float x = pts[3 * i + 0];
    float y = pts[3 * i + 1];
    float z = pts[3 * i + 2];
    if (!(z > 0.1f && z < 10.0f)) return;

    int cx = (int)rintf((x + 1.0f) * 0.5f * 511.0f);
    int cy = (int)rintf((y + 1.0f) * 0.5f * 511.0f);
    int px0 = max(cx - RR, 0), px1 = min(cx + RR, WW - 1);
    int py0 = max(cy - RR, 0), py1 = min(cy + RR, HH - 1);
    if (px0 > px1 || py0 > py1) return;

    int tx0 = px0 >> 3, tx1 = px1 >> 3;              // TW = 8
    int ty0 = py0 >> 2, ty1 = py1 >> 2;              // TH = 4
    int tb = (i >= PP) ? TILES_IMG : 0;

    for (int ty = ty0; ty <= ty1; ++ty)
        for (int tx = tx0; tx <= tx1; ++tx) {
            int t = tb + ty * TILES_X + tx;
            int slot = atomicAdd(&g_cnt[t], 1);
            if (slot < CAP) g_list[t * CAP + slot] = i;
        }
}

// ---------------------------------------------------------------------------
// Gather: one warp per tile, one thread per pixel, BRANCHLESS inner loop with
// packed f32x2 accumulation. Stabilizer-free weights w' = ws*exp(-2z) (exact
// cancellation in color/depth; verified R2-R6). Cull math (qxn/qyn/d2 and the
// d2<=r2 compare) bit-identical to the passing R1-R6 kernels; the exp(-2z)
// factor is folded into staged per-candidate constants (ez, ez*z, ez*f[8]),
// each a ~1-ulp perturbation of the prior weights.
__global__ void __launch_bounds__(32) k_gather(
        const float* __restrict__ pts,
        const float* __restrict__ feat,
        const float* __restrict__ sig,
        const float* __restrict__ mr_ptr,
        float* __restrict__ out) {
    __shared__ float4 sA[CHUNK];                     // x, y, inv2s2, unused
    __shared__ unsigned long long sEZ[CHUNK];        // (ez, ez*z)
    __shared__ ulonglong2 sF[CHUNK * 2];             // ez*f packed as 4x f32x2

    int t = blockIdx.x;
    int b = t >> 13;                                 // / TILES_IMG (8192)
    int r = t & (TILES_IMG - 1);
    int ty = r >> 6;                                 // / TILES_X (64)
    int tx = r & (TILES_X - 1);

    int lane = threadIdx.x;
    int px = tx * TW + (lane & (TW - 1));
    int py = ty * TH + (lane >> 3);

    // Pixel NDC coords — bit-identical formula to the validated cull math.
    float qxn = __fadd_rn(__fmul_rn(2.0f, (float)px) / 511.0f, -1.0f);
    float qyn = __fadd_rn(__fmul_rn(2.0f, (float)py) / 511.0f, -1.0f);

    float mr = __ldg(mr_ptr);
    float r2 = mr * mr;

    int cnt = g_cnt[t];
    if (cnt > CAP) cnt = CAP;

    const float4* ff = (const float4*)feat;

    float accWS = 0.f;
    unsigned long long aW = 0ull;                    // (accW, accWZ)
    unsigned long long a01 = 0ull, a23 = 0ull, a45 = 0ull, a67 = 0ull;

    for (int c0 = 0; c0 < cnt; c0 += CHUNK) {
        int m = min(CHUNK, cnt - c0);
        if (lane < m) {
            int j = g_list[t * CAP + c0 + lane];
            float x = pts[3 * j + 0];
            float y = pts[3 * j + 1];
            float z = pts[3 * j + 2];
            float s = sig[j];
            float sinv = 1.0f / (2.0f * s * s);
            float ez = __expf(-2.0f * z);            // GAMMA = 0.5
            sA[lane] = make_float4(x, y, sinv, 0.0f);
            sEZ[lane] = pack2(ez, ez * z);
            float4 fa = ff[2 * j + 0];
            float4 fb = ff[2 * j + 1];
            sF[2 * lane + 0] = make_ulonglong2(pack2(ez * fa.x, ez * fa.y),
                                               pack2(ez * fa.z, ez * fa.w));
            sF[2 * lane + 1] = make_ulonglong2(pack2(ez * fb.x, ez * fb.y),
                                               pack2(ez * fb.z, ez * fb.w));
        }
        __syncwarp();

#pragma unroll 4
        for (int k = 0; k < m; ++k) {
            float4 A = sA[k];
            float dx = __fadd_rn(qxn, -A.x);
            float dy = __fadd_rn(qyn, -A.y);
            float d2 = __fadd_rn(__fmul_rn(dx, dx), __fmul_rn(dy, dy));
            float e  = __expf(-d2 * A.z);
            float ws = (d2 <= r2) ? e : 0.0f;        // SEL, no branch
            accWS += ws;                             // +0 exactly on miss
            unsigned long long w2;
            asm("mov.b64 %0, {%1, %1};" : "=l"(w2) : "r"(__float_as_uint(ws)));
            ffma2(aW, w2, sEZ[k]);                   // accW += ws*ez; accWZ += ws*ez*z
            ulonglong2 f01 = sF[2 * k + 0];
            ulonglong2 f23 = sF[2 * k + 1];
            ffma2(a01, w2, f01.x);
            ffma2(a23, w2, f01.y);
            ffma2(a45, w2, f23.x);
            ffma2(a67, w2, f23.y);
        }
        __syncwarp();
    }

    float accW, accWZ, f0, f1, f2, f3, f4v, f5, f6, f7;
    unpack2(aW, accW, accWZ);
    unpack2(a01, f0, f1);
    unpack2(a23, f2, f3);
    unpack2(a45, f4v, f5);
    unpack2(a67, f6, f7);

    int pix = b * (HH * WW) + py * WW + px;
    float inv = (accW > 0.0f) ? (1.0f / accW) : 0.0f;

    float4* col = (float4*)out;
    col[2 * pix + 0] = make_float4(f0 * inv, f1 * inv, f2 * inv, f3 * inv);
    col[2 * pix + 1] = make_float4(f4v * inv, f5 * inv, f6 * inv, f7 * inv);
    out[NPIX * CC + pix]        = accWZ * inv;           // depth
    out[NPIX * CC + NPIX + pix] = 1.0f - expf(-accWS);   // mask

    // Reset counter for next graph replay. All lanes loaded g_cnt[t] before
    // this store (same warp), so the reset cannot race the reads.
    if (lane == 0) g_cnt[t] = 0;
}

// ---------------------------------------------------------------------------
extern "C" void kernel_launch(void* const* d_in, const int* in_sizes, int n_in,
                              void* d_out, int out_size) {
    const float* pts  = (const float*)d_in[0];  // [B,P,3]
    const float* feat = (const float*)d_in[1];  // [B,P,8]
    const float* sig  = (const float*)d_in[2];  // [B,P]
    const float* mr   = (const float*)d_in[3];  // scalar
    float* out = (float*)d_out;

    k_bin   <<<NPTS / 256, 256>>>(pts);
    k_gather<<<NTILES, 32>>>(pts, feat, sig, mr, out);
}

// round 8
// speedup vs baseline: 1.3485x; 1.0938x over previous
#include <cuda_runtime.h>
#include <cuda_bf16.h>

// Problem constants (match reference)
#define HH 512
#define WW 512
#define RR 4
#define BB 2
#define PP 65536
#define CC 8
#define NPTS (BB * PP)
#define NPIX (BB * HH * WW)

// Tiling: 8 x 4 pixel tiles; each CTA = 64 threads = 2 warps = 2 tiles.
#define TW 8
#define TH 4
#define TILES_X (WW / TW)              // 64
#define TILES_Y (HH / TH)              // 128
#define TILES_IMG (TILES_X * TILES_Y)  // 8192
#define NTILES (BB * TILES_IMG)        // 16384
#define CAP 128                        // per-tile capacity (mean ~36 after prefilter)
#define CHUNK 32                       // candidates staged per warp round

__device__ int g_cnt[NTILES];          // zero at load; gather resets after use
__device__ int g_list[NTILES * CAP];

// NDC coordinate of a pixel center — the single validated formula.
#define NDC(p) __fadd_rn(__fmul_rn(2.0f, (float)(p)) / 511.0f, -1.0f)

// ---------------------------------------------------------------------------
__device__ __forceinline__ unsigned long long pack2(float a, float b) {
    unsigned long long r;
    asm("mov.b64 %0, {%1, %2};" : "=l"(r) : "r"(__float_as_uint(a)), "r"(__float_as_uint(b)));
    return r;
}
__device__ __forceinline__ void unpack2(unsigned long long v, float& a, float& b) {
    unsigned int lo, hi;
    asm("mov.b64 {%0, %1}, %2;" : "=r"(lo), "=r"(hi) : "l"(v));
    a = __uint_as_float(lo);
    b = __uint_as_float(hi);
}
__device__ __forceinline__ void ffma2(unsigned long long& acc,
                                      unsigned long long a,
                                      unsigned long long b) {
    asm("fma.rn.f32x2 %0, %1, %2, %0;" : "+l"(acc) : "l"(a), "l"(b));
}

// ---------------------------------------------------------------------------
// Bin each valid point into the 8x4 tiles its disc can actually touch.
// Circle-vs-tile prefilter: clamp the point to the tile's pixel-center
// rectangle in NDC; if even that closest continuous position is outside the
// radius (with conservative margin), no pixel of the tile can pass the exact
// d2 <= r2 cull in gather, so the insert is skipped. Falsely-kept candidates
// are harmless (gather re-tests exactly); falsely-dropped are impossible
// (discrete min distance >= continuous min distance, margin covers rounding).
__global__ void __launch_bounds__(256) k_bin(const float* __restrict__ pts,
                                             const float* __restrict__ mr_ptr) {
    int i = blockIdx.x * blockDim.x + threadIdx.x;   // NPTS divisible by 256
    float x = pts[3 * i + 0];
    float y = pts[3 * i + 1];
    float z = pts[3 * i + 2];
    if (!(z > 0.1f && z < 10.0f)) return;

    int cx = (int)rintf((x + 1.0f) * 0.5f * 511.0f);
    int cy = (int)rintf((y + 1.0f) * 0.5f * 511.0f);
    int px0 = max(cx - RR, 0), px1 = min(cx + RR, WW - 1);
    int py0 = max(cy - RR, 0), py1 = min(cy + RR, HH - 1);
    if (px0 > px1 || py0 > py1) return;

    float mr = __ldg(mr_ptr);
    float r2m = mr * mr * 1.000002f + 1e-12f;        // conservative margin

    int tx0 = px0 >> 3, tx1 = px1 >> 3;              // TW = 8
    int ty0 = py0 >> 2, ty1 = py1 >> 2;              // TH = 4
    int tb = (i >= PP) ? TILES_IMG : 0;

    for (int ty = ty0; ty <= ty1; ++ty) {
        float ly = NDC(ty * TH), hy = NDC(ty * TH + (TH - 1));
        float cyn = fminf(fmaxf(y, ly), hy);
        float ddy = cyn - y;
        float dy2 = ddy * ddy;
        for (int tx = tx0; tx <= tx1; ++tx) {
            float lx = NDC(tx * TW), hx = NDC(tx * TW + (TW - 1));
            float cxn = fminf(fmaxf(x, lx), hx);
            float ddx = cxn - x;
            if (ddx * ddx + dy2 <= r2m) {
                int t = tb + ty * TILES_X + tx;
                int slot = atomicAdd(&g_cnt[t], 1);
                if (slot < CAP) g_list[t * CAP + slot] = i;
            }
        }
    }
}

// ---------------------------------------------------------------------------
// Gather: 2 warps per CTA, each warp owns one tile; one thread per pixel;
// branchless inner loop with packed f32x2 accumulation (validated R7).
// Stabilizer-free weights w' = ws*exp(-2z) — exact cancellation (R2-R7).
__global__ void __launch_bounds__(64, 20) k_gather(
        const float* __restrict__ pts,
        const float* __restrict__ feat,
        const float* __restrict__ sig,
        const float* __restrict__ mr_ptr,
        float* __restrict__ out) {
    __shared__ float4 sA[2][CHUNK];                  // x, y, inv2s2, unused
    __shared__ unsigned long long sEZ[2][CHUNK];     // (ez, ez*z)
    __shared__ ulonglong2 sF[2][CHUNK * 2];          // ez*f packed as 4x f32x2

    int warp = threadIdx.x >> 5;
    int lane = threadIdx.x & 31;
    int t = blockIdx.x * 2 + warp;

    int b = t >> 13;                                 // / TILES_IMG (8192)
    int r = t & (TILES_IMG - 1);
    int ty = r >> 6;                                 // / TILES_X (64)
    int tx = r & (TILES_X - 1);

    int px = tx * TW + (lane & (TW - 1));
    int py = ty * TH + (lane >> 3);

    float qxn = NDC(px);
    float qyn = NDC(py);

    float mr = __ldg(mr_ptr);
    float r2 = mr * mr;

    int cnt = g_cnt[t];
    if (cnt > CAP) cnt = CAP;

    const float4* ff = (const float4*)feat;

    float accWS = 0.f;
    unsigned long long aW = 0ull;                    // (accW, accWZ)
    unsigned long long a01 = 0ull, a23 = 0ull, a45 = 0ull, a67 = 0ull;

    for (int c0 = 0; c0 < cnt; c0 += CHUNK) {
        int m = min(CHUNK, cnt - c0);
        if (lane < m) {
            int j = g_list[t * CAP + c0 + lane];
            float x = pts[3 * j + 0];
            float y = pts[3 * j + 1];
            float z = pts[3 * j + 2];
            float s = sig[j];
            float sinv = 1.0f / (2.0f * s * s);
            float ez = __expf(-2.0f * z);            // GAMMA = 0.5
            sA[warp][lane] = make_float4(x, y, sinv, 0.0f);
            sEZ[warp][lane] = pack2(ez, ez * z);
            float4 fa = ff[2 * j + 0];
            float4 fb = ff[2 * j + 1];
            sF[warp][2 * lane + 0] = make_ulonglong2(pack2(ez * fa.x, ez * fa.y),
                                                     pack2(ez * fa.z, ez * fa.w));
            sF[warp][2 * lane + 1] = make_ulonglong2(pack2(ez * fb.x, ez * fb.y),
                                                     pack2(ez * fb.z, ez * fb.w));
        }
        __syncwarp();

#pragma unroll 2
        for (int k = 0; k < m; ++k) {
            float4 A = sA[warp][k];
            float dx = __fadd_rn(qxn, -A.x);
            float dy = __fadd_rn(qyn, -A.y);
            float d2 = __fadd_rn(__fmul_rn(dx, dx), __fmul_rn(dy, dy));
            float e  = __expf(-d2 * A.z);
            float ws = (d2 <= r2) ? e : 0.0f;        // SEL, no branch
            accWS += ws;                             // +0 exactly on miss
            unsigned long long w2;
            asm("mov.b64 %0, {%1, %1};" : "=l"(w2) : "r"(__float_as_uint(ws)));
            ffma2(aW, w2, sEZ[warp][k]);
            ulonglong2 f01 = sF[warp][2 * k + 0];
            ulonglong2 f23 = sF[warp][2 * k + 1];
            ffma2(a01, w2, f01.x);
            ffma2(a23, w2, f01.y);
            ffma2(a45, w2, f23.x);
            ffma2(a67, w2, f23.y);
        }
        __syncwarp();
    }

    float accW, accWZ, f0, f1, f2, f3, f4v, f5, f6, f7;
    unpack2(aW, accW, accWZ);
    unpack2(a01, f0, f1);
    unpack2(a23, f2, f3);
    unpack2(a45, f4v, f5);
    unpack2(a67, f6, f7);

    int pix = b * (HH * WW) + py * WW + px;
    float inv = (accW > 0.0f) ? (1.0f / accW) : 0.0f;

    float4* col = (float4*)out;
    col[2 * pix + 0] = make_float4(f0 * inv, f1 * inv, f2 * inv, f3 * inv);
    col[2 * pix + 1] = make_float4(f4v * inv, f5 * inv, f6 * inv, f7 * inv);
    out[NPIX * CC + pix]        = accWZ * inv;           // depth
    out[NPIX * CC + NPIX + pix] = 1.0f - expf(-accWS);   // mask

    // Reset counter for next graph replay (all lanes of this warp already
    // read g_cnt[t] above).
    if (lane == 0) g_cnt[t] = 0;
}

// ---------------------------------------------------------------------------
extern "C" void kernel_launch(void* const* d_in, const int* in_sizes, int n_in,
                              void* d_out, int out_size) {
    const float* pts  = (const float*)d_in[0];  // [B,P,3]
    const float* feat = (const float*)d_in[1];  // [B,P,8]
    const float* sig  = (const float*)d_in[2];  // [B,P]
    const float* mr   = (const float*)d_in[3];  // scalar
    float* out = (float*)d_out;

    k_bin   <<<NPTS / 256, 256>>>(pts, mr);
    k_gather<<<NTILES / 2, 64>>>(pts, feat, sig, mr, out);
}